// round 3
// baseline (speedup 1.0000x reference)
#include <cuda_runtime.h>
#include <cuda_fp16.h>
#include <cstdint>

// ---------------------------------------------------------------------------
// Problem constants
// ---------------------------------------------------------------------------
#define T_  4
#define B_  4
#define C_  512
#define N_  1024          // H*W
#define NH_ 8
#define HD_ 64
#define TBAT (T_*B_)      // 16 GEMM batches
#define BCN  (B_*C_*N_)   // 2,097,152
#define TBCN (T_*BCN)     // 8,388,608
#define EPS_ 1e-5f

#define SWZ(off) ((off) ^ (((off) >> 3) & 0x70))

__device__ __forceinline__ uint32_t smem_to_u32(const void* p) {
    uint32_t a;
    asm("{ .reg .u64 t; cvta.to.shared.u64 t, %1; cvt.u32.u64 %0, t; }" : "=r"(a) : "l"(p));
    return a;
}
__device__ __forceinline__ void ldsm_x4(uint32_t* r, uint32_t addr) {
    asm volatile("ldmatrix.sync.aligned.m8n8.x4.shared.b16 {%0,%1,%2,%3}, [%4];"
                 : "=r"(r[0]), "=r"(r[1]), "=r"(r[2]), "=r"(r[3]) : "r"(addr));
}
__device__ __forceinline__ void mma16816(float* c, const uint32_t* a, const uint32_t* b) {
    asm volatile(
        "mma.sync.aligned.m16n8k16.row.col.f32.f16.f16.f32 "
        "{%0,%1,%2,%3}, {%4,%5,%6,%7}, {%8,%9}, {%0,%1,%2,%3};"
        : "+f"(c[0]), "+f"(c[1]), "+f"(c[2]), "+f"(c[3])
        : "r"(a[0]), "r"(a[1]), "r"(a[2]), "r"(a[3]), "r"(b[0]), "r"(b[1]));
}

// ---------------------------------------------------------------------------
// Device scratch (static — no allocation anywhere)
// ---------------------------------------------------------------------------
__device__ __half g_wh[4 * C_ * C_];   // fp16 hi of Wq,Wk,Wv,Wp
__device__ __half g_wl[4 * C_ * C_];   // fp16 lo (residual)
__device__ __half g_xsT[TBCN];         // input spikes, [t,b,n,c] (K-major B operand)
__device__ __half g_osT[TBCN];         // attn-output spikes, [t,b,n,c]
__device__ float  g_sq[TBCN];          // q pre-act -> spikes (in-place LIF), [t,b,d,n]
__device__ float  g_sk[TBCN];
__device__ float  g_sv[TBCN];
__device__ float  g_y [TBCN];          // o_pre scratch [t,b,n,c]
__device__ float  g_kv[TBAT * NH_ * HD_ * HD_];

// ---------------------------------------------------------------------------
// Weight prep: fp32 -> fp16 hi + fp16 lo (exact two-term split)
// ---------------------------------------------------------------------------
__global__ __launch_bounds__(256)
void prep_w_kernel(const float* __restrict__ Wq, const float* __restrict__ Wk,
                   const float* __restrict__ Wv, const float* __restrict__ Wp)
{
    int idx = blockIdx.x * blockDim.x + threadIdx.x;
    int w = idx >> 18, r = idx & ((C_ * C_) - 1);
    const float* src = (w == 0) ? Wq : (w == 1) ? Wk : (w == 2) ? Wv : Wp;
    float val = src[r];
    __half hi = __float2half_rn(val);
    __half lo = __float2half_rn(val - __half2float(hi));
    g_wh[idx] = hi;
    g_wl[idx] = lo;
}

// ---------------------------------------------------------------------------
// Input LIF with transpose: x fp32 [t,b,c,n] -> g_xsT fp16 [t,b,n,c]
// ---------------------------------------------------------------------------
__global__ __launch_bounds__(256)
void lif_in_transpose_kernel(const float* __restrict__ x)
{
    int b  = blockIdx.z;
    int c0 = blockIdx.y * 32;
    int n0 = blockIdx.x * 32;
    int tx = threadIdx.x & 31, ty = threadIdx.x >> 5;
    __shared__ float s[32][33];
    float v[4] = {0.f, 0.f, 0.f, 0.f};

    for (int t = 0; t < T_; t++) {
        #pragma unroll
        for (int r = 0; r < 4; r++) {
            int c = c0 + ty + 8 * r;
            float xv = x[(((size_t)t * B_ + b) * C_ + c) * (size_t)N_ + n0 + tx];
            float vv = v[r];
            vv = fmaf(xv - vv, 0.5f, vv);
            float sp = (vv >= 1.0f) ? 1.f : 0.f;
            v[r] = (vv >= 1.0f) ? 0.f : vv;
            s[ty + 8 * r][tx] = sp;
        }
        __syncthreads();
        #pragma unroll
        for (int r = 0; r < 4; r++) {
            int n = n0 + ty + 8 * r;
            g_xsT[(((size_t)t * B_ + b) * N_ + n) * C_ + c0 + tx] =
                __float2half(s[tx][ty + 8 * r]);
        }
        __syncthreads();
    }
}

// ---------------------------------------------------------------------------
// HMMA GEMM + BN epilogue (mma.sync m16n8k16, fp16 in / fp32 accum).
//   Y[tb, d, n] = (sum_c W[d,c] * X[tb, n, c]) * sc[d] + sh[d]
// Block tile 128(d) x 64(n), K-tile 64; hi + lo accumulate into same fp32 acc.
// fused=1: blockIdx.z = widx*16 + tb (widx 0..2 -> q/k/v); fused=0: widx=3 proj.
// ---------------------------------------------------------------------------
__global__ __launch_bounds__(256)
void gemm_mma_kernel(const __half* __restrict__ X, int fused,
                     const float* __restrict__ qg, const float* __restrict__ qb,
                     const float* __restrict__ qm, const float* __restrict__ qv,
                     const float* __restrict__ kg, const float* __restrict__ kb,
                     const float* __restrict__ km, const float* __restrict__ kv,
                     const float* __restrict__ vg, const float* __restrict__ vb,
                     const float* __restrict__ vm, const float* __restrict__ vv,
                     const float* __restrict__ pg, const float* __restrict__ pb,
                     const float* __restrict__ pm, const float* __restrict__ pv,
                     const float* __restrict__ bias,
                     float* __restrict__ Yext)
{
    __shared__ __align__(128) __half sA[2][128 * 64];   // hi, lo
    __shared__ __align__(128) __half sB[64 * 64];

    int zz = blockIdx.z;
    int widx, tb;
    if (fused) { widx = zz >> 4; tb = zz & 15; }
    else       { widx = 3;       tb = zz; }

    const float* gam = (widx == 0) ? qg : (widx == 1) ? kg : (widx == 2) ? vg : pg;
    const float* bet = (widx == 0) ? qb : (widx == 1) ? kb : (widx == 2) ? vb : pb;
    const float* mu  = (widx == 0) ? qm : (widx == 1) ? km : (widx == 2) ? vm : pm;
    const float* var = (widx == 0) ? qv : (widx == 1) ? kv : (widx == 2) ? vv : pv;
    float* Y = (widx == 0) ? g_sq : (widx == 1) ? g_sk : (widx == 2) ? g_sv : Yext;

    const __half* Whi = g_wh + (size_t)widx * (C_ * C_);
    const __half* Wlo = g_wl + (size_t)widx * (C_ * C_);
    const __half* Xb  = X + (size_t)tb * N_ * C_;

    int n0 = blockIdx.x * 64;
    int d0 = blockIdx.y * 128;
    int tid = threadIdx.x, lane = tid & 31, wid = tid >> 5;
    int wm = wid & 3, wn = wid >> 2;     // warp tile: rows wm*32, cols wn*32

    uint32_t sA0 = smem_to_u32(sA[0]);
    uint32_t sA1 = smem_to_u32(sA[1]);
    uint32_t sBu = smem_to_u32(sB);

    float acc[2][4][4];
    #pragma unroll
    for (int i = 0; i < 2; i++)
        #pragma unroll
        for (int j = 0; j < 4; j++)
            #pragma unroll
            for (int q = 0; q < 4; q++) acc[i][j][q] = 0.f;

    // ldmatrix lane addressing precompute
    int lt = lane >> 3, lr = lane & 7;
    // A tiles: (m0,k0),(m8,k0),(m0,k8),(m8,k8)
    int a_row_off = (lt & 1) * 8 + lr;
    int a_kb_off  = (lt >> 1) * 16;
    // B tiles: (n0,k0),(n0,k8),(n8,k0),(n8,k8)
    int b_row_off = (lt >> 1) * 8 + lr;
    int b_kb_off  = (lt & 1) * 16;

    for (int c0 = 0; c0 < C_; c0 += 64) {
        // ---- global -> smem ----
        #pragma unroll
        for (int it = 0; it < 4; it++) {
            int idx = tid + 256 * it;
            int row = idx >> 3, j = idx & 7;
            uint32_t so = SWZ((uint32_t)(row * 128 + j * 16));
            *reinterpret_cast<uint4*>((char*)sA[0] + so) =
                *reinterpret_cast<const uint4*>(Whi + (size_t)(d0 + row) * C_ + c0 + j * 8);
            *reinterpret_cast<uint4*>((char*)sA[1] + so) =
                *reinterpret_cast<const uint4*>(Wlo + (size_t)(d0 + row) * C_ + c0 + j * 8);
        }
        #pragma unroll
        for (int it = 0; it < 2; it++) {
            int idx = tid + 256 * it;
            int row = idx >> 3, j = idx & 7;
            uint32_t so = SWZ((uint32_t)(row * 128 + j * 16));
            *reinterpret_cast<uint4*>((char*)sB + so) =
                *reinterpret_cast<const uint4*>(Xb + (size_t)(n0 + row) * C_ + c0 + j * 8);
        }
        __syncthreads();

        // ---- 4 k-steps of 16 ----
        #pragma unroll
        for (int ks = 0; ks < 4; ks++) {
            int kB = ks * 32;   // bytes

            uint32_t bf[2][4];
            ldsm_x4(bf[0], sBu + SWZ((uint32_t)((wn * 32 + b_row_off) * 128 + kB + b_kb_off)));
            ldsm_x4(bf[1], sBu + SWZ((uint32_t)((wn * 32 + 16 + b_row_off) * 128 + kB + b_kb_off)));

            uint32_t af[2][4];
            // hi pass
            ldsm_x4(af[0], sA0 + SWZ((uint32_t)((wm * 32 + a_row_off) * 128 + kB + a_kb_off)));
            ldsm_x4(af[1], sA0 + SWZ((uint32_t)((wm * 32 + 16 + a_row_off) * 128 + kB + a_kb_off)));
            #pragma unroll
            for (int i = 0; i < 2; i++) {
                mma16816(acc[i][0], af[i], &bf[0][0]);
                mma16816(acc[i][1], af[i], &bf[0][2]);
                mma16816(acc[i][2], af[i], &bf[1][0]);
                mma16816(acc[i][3], af[i], &bf[1][2]);
            }
            // lo pass (reuse B frags)
            ldsm_x4(af[0], sA1 + SWZ((uint32_t)((wm * 32 + a_row_off) * 128 + kB + a_kb_off)));
            ldsm_x4(af[1], sA1 + SWZ((uint32_t)((wm * 32 + 16 + a_row_off) * 128 + kB + a_kb_off)));
            #pragma unroll
            for (int i = 0; i < 2; i++) {
                mma16816(acc[i][0], af[i], &bf[0][0]);
                mma16816(acc[i][1], af[i], &bf[0][2]);
                mma16816(acc[i][2], af[i], &bf[1][0]);
                mma16816(acc[i][3], af[i], &bf[1][2]);
            }
        }
        __syncthreads();
    }

    // ---- BN epilogue + store ----
    float scv[2][2], shv[2][2];
    #pragma unroll
    for (int i = 0; i < 2; i++)
        #pragma unroll
        for (int h = 0; h < 2; h++) {
            int d = d0 + wm * 32 + i * 16 + h * 8 + (lane >> 2);
            float sc = gam[d] * rsqrtf(var[d] + EPS_);
            float sh = bet[d] - mu[d] * sc;
            if (!fused) sh += bias[d] * sc;   // proj bias
            scv[i][h] = sc; shv[i][h] = sh;
        }
    #pragma unroll
    for (int i = 0; i < 2; i++) {
        #pragma unroll
        for (int j = 0; j < 4; j++) {
            int n = n0 + wn * 32 + j * 8 + (lane & 3) * 2;
            int dlo = d0 + wm * 32 + i * 16 + (lane >> 2);
            float2 v0, v1;
            v0.x = acc[i][j][0] * scv[i][0] + shv[i][0];
            v0.y = acc[i][j][1] * scv[i][0] + shv[i][0];
            v1.x = acc[i][j][2] * scv[i][1] + shv[i][1];
            v1.y = acc[i][j][3] * scv[i][1] + shv[i][1];
            *reinterpret_cast<float2*>(Y + ((size_t)tb * C_ + dlo) * N_ + n) = v0;
            *reinterpret_cast<float2*>(Y + ((size_t)tb * C_ + dlo + 8) * N_ + n) = v1;
        }
    }
}

// ---------------------------------------------------------------------------
// In-place LIF over the 3 QKV pre-activation buffers (vth = 1.0)
// ---------------------------------------------------------------------------
__global__ __launch_bounds__(256)
void lif_qkv3_kernel()
{
    int gidx = blockIdx.x * blockDim.x + threadIdx.x;   // 0 .. 3*BCN-1
    int buf = gidx / BCN;
    int idx = gidx - buf * BCN;
    float* S = (buf == 0) ? g_sq : (buf == 1) ? g_sk : g_sv;
    float v = 0.f;
    #pragma unroll
    for (int t = 0; t < T_; t++) {
        float x = S[(size_t)t * BCN + idx];
        v = fmaf(x - v, 0.5f, v);
        float s = (v >= 1.0f) ? 1.f : 0.f;
        S[(size_t)t * BCN + idx] = s;
        v = (v >= 1.0f) ? 0.f : v;
    }
}

// ---------------------------------------------------------------------------
// LIF over g_y [t,b,n,c] fp32 -> g_osT fp16 (vth=0.5)
// ---------------------------------------------------------------------------
__global__ __launch_bounds__(256)
void lif_o_kernel()
{
    int idx = blockIdx.x * blockDim.x + threadIdx.x;
    if (idx >= BCN) return;
    float v = 0.f;
    #pragma unroll
    for (int t = 0; t < T_; t++) {
        float x = g_y[(size_t)t * BCN + idx];
        v = fmaf(x - v, 0.5f, v);
        float s = (v >= 0.5f) ? 1.f : 0.f;
        g_osT[(size_t)t * BCN + idx] = __float2half(s);
        v = (v >= 0.5f) ? 0.f : v;
    }
}

// ---------------------------------------------------------------------------
// KV[e][dd] = sum_m k[tb, h*64+e, m] * v[tb, h*64+dd, m]  (per (tb,h))
// ---------------------------------------------------------------------------
__global__ __launch_bounds__(256)
void kv_kernel()
{
    int idx = blockIdx.x;
    int tb = idx >> 3, h = idx & 7;
    const float* Kb = g_sk + (size_t)tb * C_ * N_ + (size_t)h * HD_ * N_;
    const float* Vb = g_sv + (size_t)tb * C_ * N_ + (size_t)h * HD_ * N_;
    float* KVb = g_kv + (size_t)idx * HD_ * HD_;

    __shared__ float Ks[64][65];
    __shared__ float Vs[64][65];

    int tid = threadIdx.x;
    int tx = tid & 15, ty = tid >> 4;
    float acc[4][4];
    #pragma unroll
    for (int i = 0; i < 4; i++)
        #pragma unroll
        for (int j = 0; j < 4; j++) acc[i][j] = 0.f;

    for (int m0 = 0; m0 < N_; m0 += 64) {
        int mm = tid & 63, e0 = tid >> 6;
        #pragma unroll
        for (int r = 0; r < 16; r++) {
            Ks[e0 + 4 * r][mm] = Kb[(size_t)(e0 + 4 * r) * N_ + m0 + mm];
            Vs[e0 + 4 * r][mm] = Vb[(size_t)(e0 + 4 * r) * N_ + m0 + mm];
        }
        __syncthreads();
        #pragma unroll 8
        for (int mm2 = 0; mm2 < 64; mm2++) {
            float a[4], b[4];
            #pragma unroll
            for (int i = 0; i < 4; i++) a[i] = Ks[ty * 4 + i][mm2];
            #pragma unroll
            for (int j = 0; j < 4; j++) b[j] = Vs[tx * 4 + j][mm2];
            #pragma unroll
            for (int i = 0; i < 4; i++)
                #pragma unroll
                for (int j = 0; j < 4; j++)
                    acc[i][j] = fmaf(a[i], b[j], acc[i][j]);
        }
        __syncthreads();
    }
    #pragma unroll
    for (int i = 0; i < 4; i++)
        #pragma unroll
        for (int j = 0; j < 4; j++)
            KVb[(size_t)(ty * 4 + i) * HD_ + (tx * 4 + j)] = acc[i][j];
}

// ---------------------------------------------------------------------------
// o_pre[tb, n, h*64+dd] = 0.125 * sum_e q[tb, h*64+e, n] * KV[e][dd]
// Writes transposed layout [t,b,n,c] into g_y.
// ---------------------------------------------------------------------------
__global__ __launch_bounds__(128)
void qkv_apply_kernel()
{
    int idx = blockIdx.y;
    int tb = idx >> 3, h = idx & 7;
    int n = blockIdx.x * 128 + threadIdx.x;
    const float* Qb  = g_sq + (size_t)tb * C_ * N_ + (size_t)h * HD_ * N_;
    const float* KVb = g_kv + (size_t)idx * HD_ * HD_;

    __shared__ __align__(16) float KVs[HD_ * HD_];
    for (int i = threadIdx.x; i < HD_ * HD_; i += 128) KVs[i] = KVb[i];
    __syncthreads();

    float acc[64];
    #pragma unroll
    for (int d = 0; d < 64; d++) acc[d] = 0.f;

    for (int e = 0; e < 64; e++) {
        float qv = Qb[(size_t)e * N_ + n];
        const float4* row = (const float4*)(KVs + e * 64);
        #pragma unroll
        for (int dq = 0; dq < 16; dq++) {
            float4 kvv = row[dq];
            acc[dq * 4 + 0] = fmaf(qv, kvv.x, acc[dq * 4 + 0]);
            acc[dq * 4 + 1] = fmaf(qv, kvv.y, acc[dq * 4 + 1]);
            acc[dq * 4 + 2] = fmaf(qv, kvv.z, acc[dq * 4 + 2]);
            acc[dq * 4 + 3] = fmaf(qv, kvv.w, acc[dq * 4 + 3]);
        }
    }
    float* orow = g_y + ((size_t)tb * N_ + n) * C_ + h * HD_;
    #pragma unroll
    for (int q = 0; q < 16; q++) {
        float4 o;
        o.x = acc[q * 4 + 0] * 0.125f;
        o.y = acc[q * 4 + 1] * 0.125f;
        o.z = acc[q * 4 + 2] * 0.125f;
        o.w = acc[q * 4 + 3] * 0.125f;
        ((float4*)orow)[q] = o;
    }
}

// ---------------------------------------------------------------------------
// Launch
// ---------------------------------------------------------------------------
extern "C" void kernel_launch(void* const* d_in, const int* in_sizes, int n_in,
                              void* d_out, int out_size)
{
    const float* x   = (const float*)d_in[0];
    const float* Wq  = (const float*)d_in[1];
    const float* q_g = (const float*)d_in[2];
    const float* q_b = (const float*)d_in[3];
    const float* q_m = (const float*)d_in[4];
    const float* q_v = (const float*)d_in[5];
    const float* Wk  = (const float*)d_in[6];
    const float* k_g = (const float*)d_in[7];
    const float* k_b = (const float*)d_in[8];
    const float* k_m = (const float*)d_in[9];
    const float* k_v = (const float*)d_in[10];
    const float* Wv  = (const float*)d_in[11];
    const float* v_g = (const float*)d_in[12];
    const float* v_b = (const float*)d_in[13];
    const float* v_m = (const float*)d_in[14];
    const float* v_v = (const float*)d_in[15];
    const float* Wp  = (const float*)d_in[16];
    const float* bp  = (const float*)d_in[17];
    const float* p_g = (const float*)d_in[18];
    const float* p_b = (const float*)d_in[19];
    const float* p_m = (const float*)d_in[20];
    const float* p_v = (const float*)d_in[21];
    float* out = (float*)d_out;

    dim3 lif_in_grid(N_ / 32, C_ / 32, B_);

    // 0) Weight split fp32 -> fp16 hi/lo
    prep_w_kernel<<<(4 * C_ * C_) / 256, 256>>>(Wq, Wk, Wv, Wp);

    // 1) Input LIF -> transposed fp16 spikes [t,b,n,c]
    lif_in_transpose_kernel<<<lif_in_grid, 256>>>(x);

    // 2) Fused Q/K/V GEMM (HMMA) + BN -> g_sq/g_sk/g_sv, then in-place LIF
    gemm_mma_kernel<<<dim3(N_ / 64, C_ / 128, 3 * TBAT), 256>>>(
        g_xsT, 1,
        q_g, q_b, q_m, q_v, k_g, k_b, k_m, k_v, v_g, v_b, v_m, v_v,
        p_g, p_b, p_m, p_v, nullptr, nullptr);
    lif_qkv3_kernel<<<(3 * BCN) / 256, 256>>>();

    // 3) Attention (exact re-association)
    kv_kernel<<<TBAT * NH_, 256>>>();
    qkv_apply_kernel<<<dim3(N_ / 128, TBAT * NH_), 128>>>();

    // 4) attn LIF (vth=0.5) -> transposed fp16 spikes g_osT
    lif_o_kernel<<<BCN / 256, 256>>>();

    // 5) Projection GEMM (HMMA) + bias + BN -> d_out
    gemm_mma_kernel<<<dim3(N_ / 64, C_ / 128, TBAT), 256>>>(
        g_osT, 0,
        q_g, q_b, q_m, q_v, k_g, k_b, k_m, k_v, v_g, v_b, v_m, v_v,
        p_g, p_b, p_m, p_v, bp, out);
}